// round 5
// baseline (speedup 1.0000x reference)
#include <cuda_runtime.h>

// LocalizationLoss fused single-pass reduction, single launch.
// One 256-batch tile per CTA + contention-spread atomic finish (64 slots).
// output: (B, 3, 7) f32 ; target: (B, 3, 5) f32 [presence, x, y, wh, cls]
// loss = 0.5 + mean_{b,n}[ 5*lx^2 + 5*ly^2 + 10*lwh^2 + 3*nll - 0.5*bce_term ]

#define B_TOTAL   1048576
#define NANCH     3
#define OC        7    // output channels
#define TC        5    // target channels
#define TPB       256  // threads per block == batches per block
#define NBLOCKS   (B_TOTAL / TPB)   // 4096
#define NSLOTS    64   // accumulator slots to spread L2 atomic contention

__device__ double       g_slots[NSLOTS];  // zero at load; reset by last block
__device__ unsigned int g_count;          // wraps back to 0 via atom.inc

__global__ void __launch_bounds__(TPB) ll_main_kernel(const float* __restrict__ gout,
                                                      const float* __restrict__ gtgt,
                                                      float* __restrict__ out) {
    __shared__ float sOut[TPB * NANCH * OC];   // 21504 B
    __shared__ float sTgt[TPB * NANCH * TC];   // 15360 B
    __shared__ float wsum[TPB / 32];
    __shared__ bool  isLast;

    const int tid = threadIdx.x;
    const long long blockBase = (long long)blockIdx.x * TPB;

    // -------- coalesced float4 staging (spans are 16B-aligned) --------
    const float4* g4o = reinterpret_cast<const float4*>(gout + blockBase * (NANCH * OC));
    const float4* g4t = reinterpret_cast<const float4*>(gtgt + blockBase * (NANCH * TC));
    float4* s4o = reinterpret_cast<float4*>(sOut);
    float4* s4t = reinterpret_cast<float4*>(sTgt);

    constexpr int N4O = TPB * NANCH * OC / 4;  // 1344
    constexpr int N4T = TPB * NANCH * TC / 4;  //  960
    #pragma unroll
    for (int i = tid; i < N4O; i += TPB) s4o[i] = g4o[i];
    #pragma unroll
    for (int i = tid; i < N4T; i += TPB) s4t[i] = g4t[i];
    __syncthreads();

    // -------- per-batch loss terms (strides 21/15 odd -> conflict-free) --------
    const float* o  = sOut + tid * (NANCH * OC);
    const float* tg = sTgt + tid * (NANCH * TC);

    float acc = 0.0f;
    float l[NANCH][3];   // masked class logits, l[anchor][class]
    int   cls[NANCH];

    #pragma unroll
    for (int n = 0; n < NANCH; n++) {
        const float p = o[n * OC + 0];
        const float t = tg[n * TC + 0];

        // bce term: t*log(p) + (1-t)*log(1-p)
        const float bce = t * __logf(p) + (1.0f - t) * __logf(1.0f - p);

        const float mask = (t != 0.0f) ? 1.0f : 0.0f;

        const float lx = mask * o[n * OC + 1] - tg[n * TC + 1];
        const float ly = mask * o[n * OC + 2] - tg[n * TC + 2];

        // sq_pred = mask ? sqrt(out_wh) : 0   (out_wh in (0,1), sqrt always valid)
        const float sp  = mask * __fsqrt_rn(o[n * OC + 3]);
        const float lwh = sp - __fsqrt_rn(tg[n * TC + 3]);

        acc += 5.0f * (lx * lx + ly * ly) + 10.0f * (lwh * lwh) - 0.5f * bce;

        cls[n] = (int)tg[n * TC + 4];
        #pragma unroll
        for (int c = 0; c < 3; c++) l[n][c] = mask * o[n * OC + 4 + c];
    }

    // log_softmax over anchors (axis=1) per class column, then NLL gather
    #pragma unroll
    for (int c = 0; c < 3; c++) {
        const float m = fmaxf(l[0][c], fmaxf(l[1][c], l[2][c]));
        const float s = __expf(l[0][c] - m) + __expf(l[1][c] - m) + __expf(l[2][c] - m);
        const float lse = m + __logf(s);
        const float sel = (cls[c] == 0) ? l[0][c] : ((cls[c] == 1) ? l[1][c] : l[2][c]);
        acc += 3.0f * (lse - sel);
    }

    // -------- block reduction --------
    #pragma unroll
    for (int off = 16; off > 0; off >>= 1)
        acc += __shfl_xor_sync(0xFFFFFFFFu, acc, off);
    if ((tid & 31) == 0) wsum[tid >> 5] = acc;
    __syncthreads();

    if (tid == 0) {
        float s = 0.0f;
        #pragma unroll
        for (int w = 0; w < TPB / 32; w++) s += wsum[w];
        // spread fp64 RMW contention across 64 L2 addresses
        atomicAdd(&g_slots[blockIdx.x & (NSLOTS - 1)], (double)s);
        // acq_rel inc with wraparound: release-orders the add above,
        // self-resets the counter, acquire for the last block. No threadfence.
        unsigned int prev;
        asm volatile("atom.acq_rel.gpu.global.inc.u32 %0, [%1], %2;"
                     : "=r"(prev)
                     : "l"(&g_count), "r"((unsigned int)(NBLOCKS - 1))
                     : "memory");
        isLast = (prev == NBLOCKS - 1);
    }
    __syncthreads();

    if (isLast && tid == 0) {
        double tot = 0.0;
        #pragma unroll
        for (int i = 0; i < NSLOTS; i++) {
            // atomic exchange: reads latest L2 value AND resets slot for next replay
            unsigned long long bits = atomicExch(
                reinterpret_cast<unsigned long long*>(&g_slots[i]), 0ULL);
            tot += __longlong_as_double((long long)bits);
        }
        out[0] = (float)(0.5 + tot / (double)((long long)B_TOTAL * NANCH));
    }
}

extern "C" void kernel_launch(void* const* d_in, const int* in_sizes, int n_in,
                              void* d_out, int out_size) {
    // Identify inputs by element count (output: B*21, target: B*15)
    const float* gout = (const float*)d_in[0];
    const float* gtgt = (const float*)d_in[1];
    if (n_in >= 2 && in_sizes[0] == B_TOTAL * NANCH * TC) {
        gout = (const float*)d_in[1];
        gtgt = (const float*)d_in[0];
    }

    ll_main_kernel<<<NBLOCKS, TPB>>>(gout, gtgt, (float*)d_out);
}

// round 6
// speedup vs baseline: 1.0944x; 1.0944x over previous
#include <cuda_runtime.h>

// LocalizationLoss fused single-pass reduction, single launch.
// R1 streaming body + minimal epilogue: 1 relaxed fp64 atomicAdd + 1 RELEASE
// (not acq_rel) inc per CTA. Last block reads via atomicExch (L2 RMW = fresh).
// output: (B, 3, 7) f32 ; target: (B, 3, 5) f32 [presence, x, y, wh, cls]
// loss = 0.5 + mean_{b,n}[ 5*lx^2 + 5*ly^2 + 10*lwh^2 + 3*nll - 0.5*bce_term ]

#define B_TOTAL   1048576
#define NANCH     3
#define OC        7    // output channels
#define TC        5    // target channels
#define TPB       256  // threads per block == batches per block
#define NBLOCKS   (B_TOTAL / TPB)   // 4096

__device__ double       g_acc;     // zero at load; reset by last block each run
__device__ unsigned int g_count;   // wraps back to 0 via atom.inc

__global__ void __launch_bounds__(TPB) ll_main_kernel(const float* __restrict__ gout,
                                                      const float* __restrict__ gtgt,
                                                      float* __restrict__ out) {
    __shared__ float sOut[TPB * NANCH * OC];   // 21504 B
    __shared__ float sTgt[TPB * NANCH * TC];   // 15360 B
    __shared__ float wsum[TPB / 32];
    __shared__ bool  isLast;

    const int tid = threadIdx.x;
    const long long blockBase = (long long)blockIdx.x * TPB;

    // -------- coalesced float4 staging (spans are 16B-aligned) --------
    const float4* g4o = reinterpret_cast<const float4*>(gout + blockBase * (NANCH * OC));
    const float4* g4t = reinterpret_cast<const float4*>(gtgt + blockBase * (NANCH * TC));
    float4* s4o = reinterpret_cast<float4*>(sOut);
    float4* s4t = reinterpret_cast<float4*>(sTgt);

    constexpr int N4O = TPB * NANCH * OC / 4;  // 1344
    constexpr int N4T = TPB * NANCH * TC / 4;  //  960
    #pragma unroll
    for (int i = tid; i < N4O; i += TPB) s4o[i] = g4o[i];
    #pragma unroll
    for (int i = tid; i < N4T; i += TPB) s4t[i] = g4t[i];
    __syncthreads();

    // -------- per-batch loss terms (strides 21/15 odd -> conflict-free) --------
    const float* o  = sOut + tid * (NANCH * OC);
    const float* tg = sTgt + tid * (NANCH * TC);

    float acc = 0.0f;
    float l[NANCH][3];   // masked class logits, l[anchor][class]
    int   cls[NANCH];

    #pragma unroll
    for (int n = 0; n < NANCH; n++) {
        const float p = o[n * OC + 0];
        const float t = tg[n * TC + 0];

        // bce term: t*log(p) + (1-t)*log(1-p)
        const float bce = t * __logf(p) + (1.0f - t) * __logf(1.0f - p);

        const float mask = (t != 0.0f) ? 1.0f : 0.0f;

        const float lx = mask * o[n * OC + 1] - tg[n * TC + 1];
        const float ly = mask * o[n * OC + 2] - tg[n * TC + 2];

        // sq_pred = mask ? sqrt(out_wh) : 0   (out_wh in (0,1), sqrt always valid)
        const float sp  = mask * __fsqrt_rn(o[n * OC + 3]);
        const float lwh = sp - __fsqrt_rn(tg[n * TC + 3]);

        acc += 5.0f * (lx * lx + ly * ly) + 10.0f * (lwh * lwh) - 0.5f * bce;

        cls[n] = (int)tg[n * TC + 4];
        #pragma unroll
        for (int c = 0; c < 3; c++) l[n][c] = mask * o[n * OC + 4 + c];
    }

    // log_softmax over anchors (axis=1) per class column, then NLL gather
    #pragma unroll
    for (int c = 0; c < 3; c++) {
        const float m = fmaxf(l[0][c], fmaxf(l[1][c], l[2][c]));
        const float s = __expf(l[0][c] - m) + __expf(l[1][c] - m) + __expf(l[2][c] - m);
        const float lse = m + __logf(s);
        const float sel = (cls[c] == 0) ? l[0][c] : ((cls[c] == 1) ? l[1][c] : l[2][c]);
        acc += 3.0f * (lse - sel);
    }

    // -------- block reduction --------
    #pragma unroll
    for (int off = 16; off > 0; off >>= 1)
        acc += __shfl_xor_sync(0xFFFFFFFFu, acc, off);
    if ((tid & 31) == 0) wsum[tid >> 5] = acc;
    __syncthreads();

    if (tid == 0) {
        float s = 0.0f;
        #pragma unroll
        for (int w = 0; w < TPB / 32; w++) s += wsum[w];
        // relaxed fp64 RMW at L2 (identical to R1's proven-fast epilogue)
        atomicAdd(&g_acc, (double)s);
        // RELEASE-only inc (no acquire -> no L1-side ordering cost):
        // orders the add above to L2, wraps to 0 for graph-replay determinism.
        unsigned int prev;
        asm volatile("atom.release.gpu.global.inc.u32 %0, [%1], %2;"
                     : "=r"(prev)
                     : "l"(&g_count), "r"((unsigned int)(NBLOCKS - 1))
                     : "memory");
        isLast = (prev == NBLOCKS - 1);
    }
    __syncthreads();

    if (isLast && tid == 0) {
        // atomicExch is an L2 RMW: always observes the latest L2 value
        // (all contributing adds were release-ordered before their incs),
        // and resets g_acc for the next graph replay.
        unsigned long long bits =
            atomicExch(reinterpret_cast<unsigned long long*>(&g_acc), 0ULL);
        const double tot = __longlong_as_double((long long)bits);
        out[0] = (float)(0.5 + tot / (double)((long long)B_TOTAL * NANCH));
    }
}

extern "C" void kernel_launch(void* const* d_in, const int* in_sizes, int n_in,
                              void* d_out, int out_size) {
    // Identify inputs by element count (output: B*21, target: B*15)
    const float* gout = (const float*)d_in[0];
    const float* gtgt = (const float*)d_in[1];
    if (n_in >= 2 && in_sizes[0] == B_TOTAL * NANCH * TC) {
        gout = (const float*)d_in[1];
        gtgt = (const float*)d_in[0];
    }

    ll_main_kernel<<<NBLOCKS, TPB>>>(gout, gtgt, (float*)d_out);
}

// round 7
// speedup vs baseline: 1.2368x; 1.1301x over previous
#include <cuda_runtime.h>
#include <cstdint>

// LocalizationLoss fused reduction, single launch, persistent CTAs with a
// cp.async double-buffered pipeline (loads always in flight during compute).
// output: (B, 3, 7) f32 ; target: (B, 3, 5) f32 [presence, x, y, wh, cls]
// loss = 0.5 + mean_{b,n}[ 5*lx^2 + 5*ly^2 + 10*lwh^2 + 3*nll - 0.5*bce_term ]

#define B_TOTAL   1048576
#define NANCH     3
#define OC        7     // output channels
#define TC        5     // target channels
#define TPB       128   // threads per block == batches per tile
#define NTILES    (B_TOTAL / TPB)       // 8192
#define GRID      888                   // 148 SMs x 6 CTAs (36.9KB smem each)

#define OUT_F     (TPB * NANCH * OC)    // 2688 floats = 10752 B
#define TGT_F     (TPB * NANCH * TC)    // 1920 floats =  7680 B
#define BUF_F     (OUT_F + TGT_F)       // 4608 floats = 18432 B per stage
#define N4O       (OUT_F / 4)           // 672
#define N4T       (TGT_F / 4)           // 480
#define SMEM_BYTES (2 * BUF_F * 4)      // 36864 B

__device__ double       g_acc;     // zero at load; reset by last block each run
__device__ unsigned int g_count;   // wraps back to 0 via atom.inc

__device__ __forceinline__ void cp_async16(uint32_t saddr, const void* gptr) {
    asm volatile("cp.async.cg.shared.global [%0], [%1], 16;"
                 :: "r"(saddr), "l"(gptr));
}
__device__ __forceinline__ void cp_commit() {
    asm volatile("cp.async.commit_group;" ::: "memory");
}
template <int N> __device__ __forceinline__ void cp_wait() {
    asm volatile("cp.async.wait_group %0;" :: "n"(N) : "memory");
}

__global__ void __launch_bounds__(TPB) ll_main_kernel(const float* __restrict__ gout,
                                                      const float* __restrict__ gtgt,
                                                      float* __restrict__ out) {
    extern __shared__ float smem[];           // 2 stages x (out | tgt)
    __shared__ float wsum[TPB / 32];
    __shared__ bool  isLast;

    const int tid = threadIdx.x;
    const uint32_t smem_u32 = (uint32_t)__cvta_generic_to_shared(smem);

    // ---- prefetch helper: stage one 128-batch tile with cp.async ----
    auto prefetch = [&](int tile, int stage) {
        const long long base = (long long)tile * TPB;
        const float4* g4o = reinterpret_cast<const float4*>(gout + base * (NANCH * OC));
        const float4* g4t = reinterpret_cast<const float4*>(gtgt + base * (NANCH * TC));
        const uint32_t sOut = smem_u32 + (uint32_t)(stage * BUF_F) * 4u;
        const uint32_t sTgt = sOut + (uint32_t)OUT_F * 4u;
        #pragma unroll
        for (int i = tid; i < N4O; i += TPB) cp_async16(sOut + i * 16u, g4o + i);
        #pragma unroll
        for (int i = tid; i < N4T; i += TPB) cp_async16(sTgt + i * 16u, g4t + i);
        cp_commit();
    };

    float acc = 0.0f;
    int p = 0;
    prefetch(blockIdx.x, 0);

    for (int tile = blockIdx.x; tile < NTILES; tile += GRID) {
        const int next = tile + GRID;
        if (next < NTILES) { prefetch(next, p ^ 1); cp_wait<1>(); }
        else               { cp_wait<0>(); }
        __syncthreads();   // all threads' cp.async data for stage p visible

        const float* o  = smem + p * BUF_F + tid * (NANCH * OC);
        const float* tg = smem + p * BUF_F + OUT_F + tid * (NANCH * TC);

        float l[NANCH][3];
        int   cls[NANCH];

        #pragma unroll
        for (int n = 0; n < NANCH; n++) {
            const float pv = o[n * OC + 0];
            const float t  = tg[n * TC + 0];

            const float bce = t * __logf(pv) + (1.0f - t) * __logf(1.0f - pv);
            const float mask = (t != 0.0f) ? 1.0f : 0.0f;

            const float lx = mask * o[n * OC + 1] - tg[n * TC + 1];
            const float ly = mask * o[n * OC + 2] - tg[n * TC + 2];

            const float sp  = mask * __fsqrt_rn(o[n * OC + 3]);
            const float lwh = sp - __fsqrt_rn(tg[n * TC + 3]);

            acc += 5.0f * (lx * lx + ly * ly) + 10.0f * (lwh * lwh) - 0.5f * bce;

            cls[n] = (int)tg[n * TC + 4];
            #pragma unroll
            for (int c = 0; c < 3; c++) l[n][c] = mask * o[n * OC + 4 + c];
        }

        // log_softmax over anchors per class column + NLL gather
        #pragma unroll
        for (int c = 0; c < 3; c++) {
            const float m = fmaxf(l[0][c], fmaxf(l[1][c], l[2][c]));
            const float s = __expf(l[0][c] - m) + __expf(l[1][c] - m) + __expf(l[2][c] - m);
            const float lse = m + __logf(s);
            const float sel = (cls[c] == 0) ? l[0][c] : ((cls[c] == 1) ? l[1][c] : l[2][c]);
            acc += 3.0f * (lse - sel);
        }

        __syncthreads();   // all done reading stage p before it becomes a prefetch target
        p ^= 1;
    }

    // -------- block reduction --------
    #pragma unroll
    for (int off = 16; off > 0; off >>= 1)
        acc += __shfl_xor_sync(0xFFFFFFFFu, acc, off);
    if ((tid & 31) == 0) wsum[tid >> 5] = acc;
    __syncthreads();

    if (tid == 0) {
        float s = 0.0f;
        #pragma unroll
        for (int w = 0; w < TPB / 32; w++) s += wsum[w];
        atomicAdd(&g_acc, (double)s);                 // relaxed fp64 RMW at L2
        // RELEASE-only inc: orders the add to L2, wraps for graph-replay determinism.
        unsigned int prev;
        asm volatile("atom.release.gpu.global.inc.u32 %0, [%1], %2;"
                     : "=r"(prev)
                     : "l"(&g_count), "r"((unsigned int)(GRID - 1))
                     : "memory");
        isLast = (prev == GRID - 1);
    }
    __syncthreads();

    if (isLast && tid == 0) {
        // L2 RMW read (always fresh) + reset for the next replay
        unsigned long long bits =
            atomicExch(reinterpret_cast<unsigned long long*>(&g_acc), 0ULL);
        const double tot = __longlong_as_double((long long)bits);
        out[0] = (float)(0.5 + tot / (double)((long long)B_TOTAL * NANCH));
    }
}

extern "C" void kernel_launch(void* const* d_in, const int* in_sizes, int n_in,
                              void* d_out, int out_size) {
    // Identify inputs by element count (output: B*21, target: B*15)
    const float* gout = (const float*)d_in[0];
    const float* gtgt = (const float*)d_in[1];
    if (n_in >= 2 && in_sizes[0] == B_TOTAL * NANCH * TC) {
        gout = (const float*)d_in[1];
        gtgt = (const float*)d_in[0];
    }

    static bool attr_set = false;
    if (!attr_set) {
        cudaFuncSetAttribute(ll_main_kernel,
                             cudaFuncAttributeMaxDynamicSharedMemorySize, SMEM_BYTES);
        attr_set = true;
    }

    ll_main_kernel<<<GRID, TPB, SMEM_BYTES>>>(gout, gtgt, (float*)d_out);
}

// round 8
// speedup vs baseline: 1.2380x; 1.0010x over previous
#include <cuda_runtime.h>
#include <cstdint>

// LocalizationLoss fused reduction, single launch, persistent CTAs.
// WARP-PRIVATE cp.async double-buffered pipelines: each warp owns a 32-batch
// tile + its own smem slice; only __syncwarp in the main loop (no CTA barriers).
// output: (B, 3, 7) f32 ; target: (B, 3, 5) f32 [presence, x, y, wh, cls]
// loss = 0.5 + mean_{b,n}[ 5*lx^2 + 5*ly^2 + 10*lwh^2 + 3*nll - 0.5*bce_term ]

#define B_TOTAL   1048576
#define NANCH     3
#define OC        7     // output channels
#define TC        5     // target channels
#define TPB       128   // 4 warps per CTA
#define WARPS_CTA (TPB / 32)
#define GRID      888                    // 148 SMs x 6 CTAs
#define NWARPS    (GRID * WARPS_CTA)     // 3552
#define WTILE     32                     // batches per warp-tile (== lanes)
#define NWTILES   (B_TOTAL / WTILE)      // 32768

#define OUT_F     (WTILE * NANCH * OC)   // 672 floats (2688 B)
#define TGT_F     (WTILE * NANCH * TC)   // 480 floats (1920 B)
#define WBUF_F    (OUT_F + TGT_F)        // 1152 floats (4608 B) per stage
#define N4O       (OUT_F / 4)            // 168 float4
#define N4T       (TGT_F / 4)            // 120 float4
#define SMEM_BYTES (WARPS_CTA * 2 * WBUF_F * 4)   // 36864 B

__device__ double       g_acc;     // zero at load; reset by last block each run
__device__ unsigned int g_count;   // wraps back to 0 via atom.inc

__device__ __forceinline__ void cp_async16(uint32_t saddr, const void* gptr) {
    asm volatile("cp.async.cg.shared.global [%0], [%1], 16;"
                 :: "r"(saddr), "l"(gptr));
}
__device__ __forceinline__ void cp_commit() {
    asm volatile("cp.async.commit_group;" ::: "memory");
}
template <int N> __device__ __forceinline__ void cp_wait() {
    asm volatile("cp.async.wait_group %0;" :: "n"(N) : "memory");
}

__global__ void __launch_bounds__(TPB) ll_main_kernel(const float* __restrict__ gout,
                                                      const float* __restrict__ gtgt,
                                                      float* __restrict__ out) {
    extern __shared__ float smem[];    // per-warp: 2 stages x (out | tgt)
    __shared__ float wsum[WARPS_CTA];
    __shared__ bool  isLast;

    const int tid  = threadIdx.x;
    const int wid  = tid >> 5;
    const int lane = tid & 31;
    const int gw   = blockIdx.x * WARPS_CTA + wid;   // global warp id

    float* wbase = smem + wid * (2 * WBUF_F);
    const uint32_t wbase_u32 = (uint32_t)__cvta_generic_to_shared(wbase);

    // ---- warp-private prefetch of one 32-batch tile ----
    auto prefetch = [&](int t, int stage) {
        const long long base = (long long)t * WTILE;
        const float4* g4o = reinterpret_cast<const float4*>(gout + base * (NANCH * OC));
        const float4* g4t = reinterpret_cast<const float4*>(gtgt + base * (NANCH * TC));
        const uint32_t sOut = wbase_u32 + (uint32_t)(stage * WBUF_F) * 4u;
        const uint32_t sTgt = sOut + (uint32_t)OUT_F * 4u;
        #pragma unroll
        for (int i = lane; i < N4O; i += 32) cp_async16(sOut + i * 16u, g4o + i);
        #pragma unroll
        for (int i = lane; i < N4T; i += 32) cp_async16(sTgt + i * 16u, g4t + i);
        cp_commit();
    };

    float acc = 0.0f;
    int p = 0;
    if (gw < NWTILES) prefetch(gw, 0);

    for (int t = gw; t < NWTILES; t += NWARPS) {
        const int next = t + NWARPS;
        if (next < NWTILES) { prefetch(next, p ^ 1); cp_wait<1>(); }
        else                { cp_wait<0>(); }
        __syncwarp();   // make lanes' staged data visible across the warp

        const float* o  = wbase + p * WBUF_F + lane * (NANCH * OC);
        const float* tg = wbase + p * WBUF_F + OUT_F + lane * (NANCH * TC);

        float l[NANCH][3];
        int   cls[NANCH];

        #pragma unroll
        for (int n = 0; n < NANCH; n++) {
            const float pv = o[n * OC + 0];
            const float tv = tg[n * TC + 0];

            const float bce = tv * __logf(pv) + (1.0f - tv) * __logf(1.0f - pv);
            const float mask = (tv != 0.0f) ? 1.0f : 0.0f;

            const float lx = mask * o[n * OC + 1] - tg[n * TC + 1];
            const float ly = mask * o[n * OC + 2] - tg[n * TC + 2];

            const float sp  = mask * __fsqrt_rn(o[n * OC + 3]);
            const float lwh = sp - __fsqrt_rn(tg[n * TC + 3]);

            acc += 5.0f * (lx * lx + ly * ly) + 10.0f * (lwh * lwh) - 0.5f * bce;

            cls[n] = (int)tg[n * TC + 4];
            #pragma unroll
            for (int c = 0; c < 3; c++) l[n][c] = mask * o[n * OC + 4 + c];
        }

        // log_softmax over anchors per class column + NLL gather
        #pragma unroll
        for (int c = 0; c < 3; c++) {
            const float m = fmaxf(l[0][c], fmaxf(l[1][c], l[2][c]));
            const float s = __expf(l[0][c] - m) + __expf(l[1][c] - m) + __expf(l[2][c] - m);
            const float lse = m + __logf(s);
            const float sel = (cls[c] == 0) ? l[0][c] : ((cls[c] == 1) ? l[1][c] : l[2][c]);
            acc += 3.0f * (lse - sel);
        }

        __syncwarp();   // all lanes done reading stage p before it is re-staged
        p ^= 1;
    }

    // -------- block reduction (once, at the end) --------
    #pragma unroll
    for (int off = 16; off > 0; off >>= 1)
        acc += __shfl_xor_sync(0xFFFFFFFFu, acc, off);
    if (lane == 0) wsum[wid] = acc;
    __syncthreads();

    if (tid == 0) {
        float s = 0.0f;
        #pragma unroll
        for (int w = 0; w < WARPS_CTA; w++) s += wsum[w];
        atomicAdd(&g_acc, (double)s);                 // relaxed fp64 RMW at L2
        // RELEASE-only inc: orders the add to L2, wraps for graph-replay determinism.
        unsigned int prev;
        asm volatile("atom.release.gpu.global.inc.u32 %0, [%1], %2;"
                     : "=r"(prev)
                     : "l"(&g_count), "r"((unsigned int)(GRID - 1))
                     : "memory");
        isLast = (prev == GRID - 1);
    }
    __syncthreads();

    if (isLast && tid == 0) {
        // L2 RMW read (always fresh) + reset for the next replay
        unsigned long long bits =
            atomicExch(reinterpret_cast<unsigned long long*>(&g_acc), 0ULL);
        const double tot = __longlong_as_double((long long)bits);
        out[0] = (float)(0.5 + tot / (double)((long long)B_TOTAL * NANCH));
    }
}

extern "C" void kernel_launch(void* const* d_in, const int* in_sizes, int n_in,
                              void* d_out, int out_size) {
    // Identify inputs by element count (output: B*21, target: B*15)
    const float* gout = (const float*)d_in[0];
    const float* gtgt = (const float*)d_in[1];
    if (n_in >= 2 && in_sizes[0] == B_TOTAL * NANCH * TC) {
        gout = (const float*)d_in[1];
        gtgt = (const float*)d_in[0];
    }

    static bool attr_set = false;
    if (!attr_set) {
        cudaFuncSetAttribute(ll_main_kernel,
                             cudaFuncAttributeMaxDynamicSharedMemorySize, SMEM_BYTES);
        attr_set = true;
    }

    ll_main_kernel<<<GRID, TPB, SMEM_BYTES>>>(gout, gtgt, (float*)d_out);
}